// round 14
// baseline (speedup 1.0000x reference)
#include <cuda_runtime.h>
#include <cuda_fp16.h>
#include <math_constants.h>
#include <cstdint>

// ============================================================================
// Exact k-NN: fp16 HFMA2 coarse scan (2 MACs/instr at FFMA issue rate)
// + exact fp32 rescore.
//   1) cvt:     fp16 copies of base/query + exact fp32 |row|^2
//   2) coarse:  thread-per-query half2 scan, 8 chains, per-thread top-16
//               per chunk on key = |b|^2 - 2*dot
//   3) merge:   37 chunk lists -> global top-32 per query
//   4) rescore: exact fp32 d2 of 32 candidates, sort, emit top-k
// R14 = third submission (R12, R13 both died to pre-execution container
// failures; session infra failure rate ~38%, so still consistent with
// randomness). Engines measured: FFMA=rt2 wall (2857us), dp4a emulated
// (2823us), mma.sync fallback (2983us), f32x2 decomposed (3156us). HFMA2 is
// the remaining native rt2-class op with 2 MACs/instr.
// ============================================================================

#define D128  128
#define NC    37        // base chunks
#define TB    64        // base rows per smem tile (64 x 256B = 16 KB)
#define KCC   16        // candidates per (query, chunk)
#define KG    32        // global coarse candidates per query
#define MAXN  262144
#define MAXQ  1024

__device__ __align__(256) __half g_bh[MAXN * D128];   // 64 MB fp16 base
__device__ __align__(256) __half g_qh[MAXQ * D128];
__device__ float g_bsq[MAXN];
__device__ float g_qsq_dummy[MAXQ];
__device__ float g_ckey[NC * KCC * MAXQ];
__device__ int   g_cidx[NC * KCC * MAXQ];
__device__ int   g_sel [MAXQ * KG];

template<int K> __device__ __forceinline__
void topk_insert(float (&td)[K], int (&ti)[K], float& kmax, float v, int idx) {
    bool done = false;
    #pragma unroll
    for (int s = 0; s < K; ++s)
        if (!done && td[s] == kmax) { td[s] = v; ti[s] = idx; done = true; }
    float m = td[0];
    #pragma unroll
    for (int s = 1; s < K; ++s) m = fmaxf(m, td[s]);
    kmax = m;
}

__device__ __forceinline__ __half2 u2h(uint32_t u) {
    __half2 h;
    *reinterpret_cast<uint32_t*>(&h) = u;
    return h;
}

// ---------------------------------------------------------------------------
// fp32 -> fp16 convert + exact fp32 |row|^2. One warp per row.
// ---------------------------------------------------------------------------
__global__ void cvt_kernel(const float* __restrict__ src,
                           __half* __restrict__ dst,
                           float* __restrict__ sq, int N) {
    int row = blockIdx.x * 8 + (threadIdx.x >> 5);
    if (row >= N) return;
    int lane = threadIdx.x & 31;
    float4 v = reinterpret_cast<const float4*>(src)[(size_t)row * 32 + lane];
    __half2 lo = __floats2half2_rn(v.x, v.y);
    __half2 hi = __floats2half2_rn(v.z, v.w);
    __half2* o = reinterpret_cast<__half2*>(dst) + (size_t)row * 64 + lane * 2;
    o[0] = lo; o[1] = hi;
    float s = v.x * v.x + v.y * v.y + v.z * v.z + v.w * v.w;
    #pragma unroll
    for (int off = 16; off > 0; off >>= 1) s += __shfl_xor_sync(0xFFFFFFFFu, s, off);
    if (lane == 0) sq[row] = s;
}

// ---------------------------------------------------------------------------
// Coarse scan: grid (NC, Q/256), block 256, 1 thread = 1 query.
// Query (64 half2) in registers; 64-row fp16 tiles in smem (broadcast LDS),
// reg-prefetch double buffer, 1 barrier/tile. 8 independent HFMA2 chains.
// ---------------------------------------------------------------------------
__global__ void __launch_bounds__(256)
knn_coarse_h2(const __half* __restrict__ bh,
              const __half* __restrict__ qh,
              int N, int Q) {
    __shared__ __align__(16) uint32_t sB[2][TB * 64];   // 2 x 16 KB
    __shared__ float sBsq[2][TB];

    const int tid   = threadIdx.x;
    const int chunk = blockIdx.x;
    const int qt    = blockIdx.y;

    const int chunk_len = (N + NC - 1) / NC;
    const int cs = chunk * chunk_len;
    const int ce = min(cs + chunk_len, N);
    const int ntiles = (ce - cs + TB - 1) / TB;

    const uint4* b16 = reinterpret_cast<const uint4*>(bh);   // 16 uint4 per row

    // query row -> 64 half2 registers
    __half2 q2[64];
    {
        int q = min(qt * 256 + tid, Q - 1);
        const uint4* qrow = reinterpret_cast<const uint4*>(qh + (size_t)q * D128);
        #pragma unroll
        for (int i = 0; i < 16; ++i) {
            uint4 u = qrow[i];
            q2[4 * i + 0] = u2h(u.x); q2[4 * i + 1] = u2h(u.y);
            q2[4 * i + 2] = u2h(u.z); q2[4 * i + 3] = u2h(u.w);
        }
    }

    float td[KCC]; int ti[KCC];
    #pragma unroll
    for (int j = 0; j < KCC; ++j) { td[j] = CUDART_INF_F; ti[j] = -1; }
    float kmax = CUDART_INF_F;

    // prologue: tile 0 -> buffer 0  (tile = 64 rows x 16 uint4 = 1024 uint4)
    {
        #pragma unroll
        for (int j = 0; j < 4; ++j) {
            int c = tid + j * 256;          // 0..1023
            int row = c >> 4, ch = c & 15;
            int gr = min(cs + row, N - 1);
            reinterpret_cast<uint4*>(&sB[0][0])[c] = b16[(size_t)gr * 16 + ch];
        }
        if (tid < TB) {
            int gr = cs + tid;
            sBsq[0][tid] = (gr < ce) ? g_bsq[gr] : CUDART_INF_F;
        }
        __syncthreads();
    }

    for (int t = 0; t < ntiles; ++t) {
        const int s = t & 1;
        const int n0 = cs + t * TB;
        const bool pf = (t + 1 < ntiles);

        // prefetch t+1 into registers (lands during HFMA2 phase)
        uint4 r0, r1, r2, r3; float rb = CUDART_INF_F;
        if (pf) {
            const int n0n = n0 + TB;
            { int c = tid;       int row = c >> 4, ch = c & 15;
              r0 = b16[(size_t)min(n0n + row, N - 1) * 16 + ch]; }
            { int c = tid + 256; int row = c >> 4, ch = c & 15;
              r1 = b16[(size_t)min(n0n + row, N - 1) * 16 + ch]; }
            { int c = tid + 512; int row = c >> 4, ch = c & 15;
              r2 = b16[(size_t)min(n0n + row, N - 1) * 16 + ch]; }
            { int c = tid + 768; int row = c >> 4, ch = c & 15;
              r3 = b16[(size_t)min(n0n + row, N - 1) * 16 + ch]; }
            if (tid < TB) {
                int gr = n0n + tid;
                rb = (gr < ce) ? g_bsq[gr] : CUDART_INF_F;
            }
        }

        // scan rows: 16 LDS.128 + 64 HFMA2 (8 chains) + hadd2 tree per row.
        // OOB rows carry sBsq = +INF -> key never inserted.
        const __half2 hz = __float2half2_rn(0.f);
        #pragma unroll 1
        for (int r = 0; r < TB; ++r) {
            const uint4* bp = reinterpret_cast<const uint4*>(&sB[s][r * 64]);
            __half2 a0 = hz, a1 = hz, a2 = hz, a3 = hz;
            __half2 a4 = hz, a5 = hz, a6 = hz, a7 = hz;
            #pragma unroll
            for (int i = 0; i < 8; ++i) {
                uint4 w0 = bp[2 * i];
                uint4 w1 = bp[2 * i + 1];
                a0 = __hfma2(q2[8 * i + 0], u2h(w0.x), a0);
                a1 = __hfma2(q2[8 * i + 1], u2h(w0.y), a1);
                a2 = __hfma2(q2[8 * i + 2], u2h(w0.z), a2);
                a3 = __hfma2(q2[8 * i + 3], u2h(w0.w), a3);
                a4 = __hfma2(q2[8 * i + 4], u2h(w1.x), a4);
                a5 = __hfma2(q2[8 * i + 5], u2h(w1.y), a5);
                a6 = __hfma2(q2[8 * i + 6], u2h(w1.z), a6);
                a7 = __hfma2(q2[8 * i + 7], u2h(w1.w), a7);
            }
            __half2 s0 = __hadd2(a0, a4);
            __half2 s1 = __hadd2(a1, a5);
            __half2 s2 = __hadd2(a2, a6);
            __half2 s3 = __hadd2(a3, a7);
            __half2 s4 = __hadd2(s0, s1);
            __half2 s5 = __hadd2(s2, s3);
            __half2 s6 = __hadd2(s4, s5);
            float2 f = __half22float2(s6);
            float dot = f.x + f.y;
            float key = fmaf(-2.0f, dot, sBsq[s][r]);
            if (key < kmax) topk_insert(td, ti, kmax, key, n0 + r);
        }

        // store prefetched tile into other buffer, single barrier
        if (pf) {
            const int s1 = s ^ 1;
            reinterpret_cast<uint4*>(&sB[s1][0])[tid]       = r0;
            reinterpret_cast<uint4*>(&sB[s1][0])[tid + 256] = r1;
            reinterpret_cast<uint4*>(&sB[s1][0])[tid + 512] = r2;
            reinterpret_cast<uint4*>(&sB[s1][0])[tid + 768] = r3;
            if (tid < TB) sBsq[s1][tid] = rb;
        }
        __syncthreads();
    }

    // write candidates (transposed layout for coalesced merge reads)
    int q = qt * 256 + tid;
    if (q < Q) {
        #pragma unroll
        for (int j = 0; j < KCC; ++j) {
            g_ckey[(chunk * KCC + j) * MAXQ + q] = td[j];
            g_cidx[(chunk * KCC + j) * MAXQ + q] = ti[j];
        }
    }
}

// ---------------------------------------------------------------------------
// Merge NC*KCC chunk candidates -> global top-32 per query
// ---------------------------------------------------------------------------
__global__ void merge_kernel(int Q) {
    int q = blockIdx.x * blockDim.x + threadIdx.x;
    if (q >= Q) return;
    float td[KG]; int ti[KG];
    #pragma unroll
    for (int j = 0; j < KG; ++j) { td[j] = CUDART_INF_F; ti[j] = -1; }
    float kmax = CUDART_INF_F;
    for (int j = 0; j < NC * KCC; ++j) {
        float v = g_ckey[j * MAXQ + q];
        if (v < kmax) topk_insert(td, ti, kmax, v, g_cidx[j * MAXQ + q]);
    }
    #pragma unroll
    for (int j = 0; j < KG; ++j) g_sel[q * KG + j] = ti[j];
}

// ---------------------------------------------------------------------------
// Exact fp32 rescore of 32 candidates/query + final sort + output.
// 1 warp per query, lane = candidate.
// ---------------------------------------------------------------------------
__global__ void rescore_kernel(const float* __restrict__ base,
                               const float* __restrict__ query,
                               float* __restrict__ out, int N, int Q, int K) {
    __shared__ float sD[4][KG];
    __shared__ int   sI[4][KG];
    int w = threadIdx.x >> 5;
    int lane = threadIdx.x & 31;
    int q = blockIdx.x * 4 + w;
    if (q >= Q) return;

    int cand = g_sel[q * KG + lane];
    float d2;
    if (cand >= 0) {
        const float4* qrow = reinterpret_cast<const float4*>(query) + (size_t)q * 32;
        const float4* brow = reinterpret_cast<const float4*>(base) + (size_t)cand * 32;
        float dot = 0.f, qsq = 0.f;
        #pragma unroll
        for (int j = 0; j < 32; ++j) {
            float4 a = qrow[j], b = brow[j];
            dot += a.x * b.x + a.y * b.y + a.z * b.z + a.w * b.w;
            qsq += a.x * a.x + a.y * a.y + a.z * a.z + a.w * a.w;
        }
        d2 = qsq - 2.0f * dot + g_bsq[cand];
    } else {
        d2 = CUDART_INF_F; cand = 0x7fffffff;
    }
    sD[w][lane] = d2; sI[w][lane] = cand;
    __syncwarp();

    if (lane == 0) {
        float a[KG]; int b[KG];
        #pragma unroll
        for (int j = 0; j < KG; ++j) { a[j] = sD[w][j]; b[j] = sI[w][j]; }
        for (int r = 0; r < K; ++r) {
            int best = r;
            for (int j = r + 1; j < KG; ++j)
                if (a[j] < a[best] || (a[j] == a[best] && b[j] < b[best])) best = j;
            float tv = a[r]; a[r] = a[best]; a[best] = tv;
            int   ts = b[r]; b[r] = b[best]; b[best] = ts;
            out[(size_t)q * K + r]                 = (float)b[r];
            out[(size_t)Q * K + (size_t)q * K + r] = sqrtf(fmaxf(a[r], 0.0f));
        }
    }
}

// ---------------------------------------------------------------------------
extern "C" void kernel_launch(void* const* d_in, const int* in_sizes, int n_in,
                              void* d_out, int out_size) {
    const float* base  = (const float*)d_in[0];
    const float* query = (const float*)d_in[1];

    int N = in_sizes[0] / D128;
    int Q = in_sizes[1] / D128;
    int K = (Q > 0) ? out_size / (2 * Q) : 10;
    if (K <= 0 || K > KG) K = 10;

    __half* bh;  cudaGetSymbolAddress((void**)&bh, g_bh);
    __half* qhp; cudaGetSymbolAddress((void**)&qhp, g_qh);
    float* bsq;  cudaGetSymbolAddress((void**)&bsq, g_bsq);
    float* qsqd; cudaGetSymbolAddress((void**)&qsqd, g_qsq_dummy);

    cvt_kernel<<<(N + 7) / 8, 256>>>(base, bh, bsq, N);
    cvt_kernel<<<(Q + 7) / 8, 256>>>(query, qhp, qsqd, Q);

    dim3 grid(NC, (Q + 255) / 256);
    knn_coarse_h2<<<grid, 256>>>(bh, qhp, N, Q);

    merge_kernel<<<(Q + 255) / 256, 256>>>(Q);
    rescore_kernel<<<(Q + 3) / 4, 128>>>(base, query, (float*)d_out, N, Q, K);
}

// round 16
// speedup vs baseline: 1.0735x; 1.0735x over previous
#include <cuda_runtime.h>
#include <math_constants.h>
#include <cstdint>

// ============================================================================
// Exact k-NN, fp32 FFMA throughout — engine search concluded: FFMA is the
// only non-emulated MAC path on this toolchain (dp4a/mma/f32x2/HFMA2 all
// decompose). R16 = R15 resubmit (pre-execution container infra failure,
// kernel never ran). Native FFMA engine x proven R9/R11 skeleton:
// reg-prefetch double buffer, 1 barrier/tile, 8 independent FFMA chains.
//   1) bsq:     |b|^2 per base row
//   2) coarse:  thread-per-query FFMA scan, EXACT top-10 per chunk
//               on key = |b|^2 - 2*dot (global top-10 provably covered)
//   3) merge:   37 chunk lists -> global top-32 per query
//   4) rescore: exact fp32 d2 of 32 candidates, sort, emit top-k
// ============================================================================

#define D128  128
#define NC    37        // base chunks
#define TB    32        // base rows per smem tile (32 x 512B = 16 KB)
#define KCC   10        // candidates per (query, chunk) — exact coverage
#define KG    32        // global coarse candidates per query
#define MAXN  262144
#define MAXQ  1024

__device__ float g_bsq[MAXN];
__device__ float g_ckey[NC * KCC * MAXQ];
__device__ int   g_cidx[NC * KCC * MAXQ];
__device__ int   g_sel [MAXQ * KG];

template<int K> __device__ __forceinline__
void topk_insert(float (&td)[K], int (&ti)[K], float& kmax, float v, int idx) {
    bool done = false;
    #pragma unroll
    for (int s = 0; s < K; ++s)
        if (!done && td[s] == kmax) { td[s] = v; ti[s] = idx; done = true; }
    float m = td[0];
    #pragma unroll
    for (int s = 1; s < K; ++s) m = fmaxf(m, td[s]);
    kmax = m;
}

// ---------------------------------------------------------------------------
// |row|^2, one warp per row.
// ---------------------------------------------------------------------------
__global__ void bsq_kernel(const float* __restrict__ src,
                           float* __restrict__ sq, int N) {
    int row = blockIdx.x * 8 + (threadIdx.x >> 5);
    if (row >= N) return;
    int lane = threadIdx.x & 31;
    float4 v = reinterpret_cast<const float4*>(src)[(size_t)row * 32 + lane];
    float s = v.x * v.x + v.y * v.y + v.z * v.z + v.w * v.w;
    #pragma unroll
    for (int off = 16; off > 0; off >>= 1) s += __shfl_xor_sync(0xFFFFFFFFu, s, off);
    if (lane == 0) sq[row] = s;
}

// ---------------------------------------------------------------------------
// Coarse scan: grid (NC, Q/256), block 256, 1 thread = 1 query.
// Query row (32 float4) in registers; 32-row fp32 tiles in smem (broadcast
// LDS.128), reg-prefetch double buffer, 1 barrier/tile.
// 2-row groups: 64 LDS.128 + 256 FFMA across 8 independent chains.
// ---------------------------------------------------------------------------
__global__ void __launch_bounds__(256)
knn_coarse_f32(const float* __restrict__ base,
               const float* __restrict__ query,
               int N, int Q) {
    __shared__ __align__(16) float sB[2][TB * D128];   // 2 x 16 KB
    __shared__ float sBsq[2][TB];

    const int tid   = threadIdx.x;
    const int chunk = blockIdx.x;
    const int qt    = blockIdx.y;

    const int chunk_len = (N + NC - 1) / NC;
    const int cs = chunk * chunk_len;
    const int ce = min(cs + chunk_len, N);
    const int ntiles = (ce - cs + TB - 1) / TB;

    const float4* base4 = reinterpret_cast<const float4*>(base);

    // query row -> 32 float4 registers
    float4 qv[32];
    {
        int q = min(qt * 256 + tid, Q - 1);
        const float4* qrow = reinterpret_cast<const float4*>(query) + (size_t)q * 32;
        #pragma unroll
        for (int i = 0; i < 32; ++i) qv[i] = qrow[i];
    }

    float td[KCC]; int ti[KCC];
    #pragma unroll
    for (int j = 0; j < KCC; ++j) { td[j] = CUDART_INF_F; ti[j] = -1; }
    float kmax = CUDART_INF_F;

    // prologue: tile 0 -> buffer 0  (tile = 32 rows x 32 float4 = 1024 float4)
    {
        #pragma unroll
        for (int j = 0; j < 4; ++j) {
            int c = tid + j * 256;          // 0..1023
            int row = c >> 5, ch = c & 31;
            int gr = min(cs + row, N - 1);
            reinterpret_cast<float4*>(&sB[0][0])[c] = base4[(size_t)gr * 32 + ch];
        }
        if (tid < TB) {
            int gr = cs + tid;
            sBsq[0][tid] = (gr < ce) ? g_bsq[gr] : CUDART_INF_F;
        }
        __syncthreads();
    }

    for (int t = 0; t < ntiles; ++t) {
        const int s = t & 1;
        const int n0 = cs + t * TB;
        const bool pf = (t + 1 < ntiles);

        // prefetch t+1 into registers (lands during FFMA phase)
        float4 r0, r1, r2, r3; float rb = CUDART_INF_F;
        if (pf) {
            const int n0n = n0 + TB;
            { int c = tid;       int row = c >> 5, ch = c & 31;
              r0 = base4[(size_t)min(n0n + row, N - 1) * 32 + ch]; }
            { int c = tid + 256; int row = c >> 5, ch = c & 31;
              r1 = base4[(size_t)min(n0n + row, N - 1) * 32 + ch]; }
            { int c = tid + 512; int row = c >> 5, ch = c & 31;
              r2 = base4[(size_t)min(n0n + row, N - 1) * 32 + ch]; }
            { int c = tid + 768; int row = c >> 5, ch = c & 31;
              r3 = base4[(size_t)min(n0n + row, N - 1) * 32 + ch]; }
            if (tid < TB) {
                int gr = n0n + tid;
                rb = (gr < ce) ? g_bsq[gr] : CUDART_INF_F;
            }
        }

        // scan 32 rows in 2-row groups: 64 LDS.128 + 256 FFMA (8 chains).
        // OOB rows carry sBsq = +INF -> key never inserted.
        #pragma unroll 1
        for (int r = 0; r < TB; r += 2) {
            const float4* b0 = reinterpret_cast<const float4*>(&sB[s][r * D128]);
            const float4* b1 = reinterpret_cast<const float4*>(&sB[s][(r + 1) * D128]);
            float a00 = 0.f, a01 = 0.f, a02 = 0.f, a03 = 0.f;
            float a10 = 0.f, a11 = 0.f, a12 = 0.f, a13 = 0.f;
            #pragma unroll
            for (int i = 0; i < 32; ++i) {
                float4 qd = qv[i];
                float4 x0 = b0[i];
                float4 x1 = b1[i];
                a00 = fmaf(qd.x, x0.x, a00);
                a01 = fmaf(qd.y, x0.y, a01);
                a02 = fmaf(qd.z, x0.z, a02);
                a03 = fmaf(qd.w, x0.w, a03);
                a10 = fmaf(qd.x, x1.x, a10);
                a11 = fmaf(qd.y, x1.y, a11);
                a12 = fmaf(qd.z, x1.z, a12);
                a13 = fmaf(qd.w, x1.w, a13);
            }
            float dot0 = (a00 + a01) + (a02 + a03);
            float dot1 = (a10 + a11) + (a12 + a13);
            float key0 = fmaf(-2.0f, dot0, sBsq[s][r]);
            float key1 = fmaf(-2.0f, dot1, sBsq[s][r + 1]);
            if (key0 < kmax) topk_insert(td, ti, kmax, key0, n0 + r);
            if (key1 < kmax) topk_insert(td, ti, kmax, key1, n0 + r + 1);
        }

        // store prefetched tile into other buffer, single barrier
        if (pf) {
            const int s1 = s ^ 1;
            reinterpret_cast<float4*>(&sB[s1][0])[tid]       = r0;
            reinterpret_cast<float4*>(&sB[s1][0])[tid + 256] = r1;
            reinterpret_cast<float4*>(&sB[s1][0])[tid + 512] = r2;
            reinterpret_cast<float4*>(&sB[s1][0])[tid + 768] = r3;
            if (tid < TB) sBsq[s1][tid] = rb;
        }
        __syncthreads();
    }

    // write candidates (transposed layout for coalesced merge reads)
    int q = qt * 256 + tid;
    if (q < Q) {
        #pragma unroll
        for (int j = 0; j < KCC; ++j) {
            g_ckey[(chunk * KCC + j) * MAXQ + q] = td[j];
            g_cidx[(chunk * KCC + j) * MAXQ + q] = ti[j];
        }
    }
}

// ---------------------------------------------------------------------------
// Merge NC*KCC chunk candidates -> global top-32 per query
// ---------------------------------------------------------------------------
__global__ void merge_kernel(int Q) {
    int q = blockIdx.x * blockDim.x + threadIdx.x;
    if (q >= Q) return;
    float td[KG]; int ti[KG];
    #pragma unroll
    for (int j = 0; j < KG; ++j) { td[j] = CUDART_INF_F; ti[j] = -1; }
    float kmax = CUDART_INF_F;
    for (int j = 0; j < NC * KCC; ++j) {
        float v = g_ckey[j * MAXQ + q];
        if (v < kmax) topk_insert(td, ti, kmax, v, g_cidx[j * MAXQ + q]);
    }
    #pragma unroll
    for (int j = 0; j < KG; ++j) g_sel[q * KG + j] = ti[j];
}

// ---------------------------------------------------------------------------
// Exact fp32 rescore of 32 candidates/query + final sort + output.
// 1 warp per query, lane = candidate.
// ---------------------------------------------------------------------------
__global__ void rescore_kernel(const float* __restrict__ base,
                               const float* __restrict__ query,
                               float* __restrict__ out, int N, int Q, int K) {
    __shared__ float sD[4][KG];
    __shared__ int   sI[4][KG];
    int w = threadIdx.x >> 5;
    int lane = threadIdx.x & 31;
    int q = blockIdx.x * 4 + w;
    if (q >= Q) return;

    int cand = g_sel[q * KG + lane];
    float d2;
    if (cand >= 0) {
        const float4* qrow = reinterpret_cast<const float4*>(query) + (size_t)q * 32;
        const float4* brow = reinterpret_cast<const float4*>(base) + (size_t)cand * 32;
        float dot = 0.f, qsq = 0.f;
        #pragma unroll
        for (int j = 0; j < 32; ++j) {
            float4 a = qrow[j], b = brow[j];
            dot += a.x * b.x + a.y * b.y + a.z * b.z + a.w * b.w;
            qsq += a.x * a.x + a.y * a.y + a.z * a.z + a.w * a.w;
        }
        d2 = qsq - 2.0f * dot + g_bsq[cand];
    } else {
        d2 = CUDART_INF_F; cand = 0x7fffffff;
    }
    sD[w][lane] = d2; sI[w][lane] = cand;
    __syncwarp();

    if (lane == 0) {
        float a[KG]; int b[KG];
        #pragma unroll
        for (int j = 0; j < KG; ++j) { a[j] = sD[w][j]; b[j] = sI[w][j]; }
        for (int r = 0; r < K; ++r) {
            int best = r;
            for (int j = r + 1; j < KG; ++j)
                if (a[j] < a[best] || (a[j] == a[best] && b[j] < b[best])) best = j;
            float tv = a[r]; a[r] = a[best]; a[best] = tv;
            int   ts = b[r]; b[r] = b[best]; b[best] = ts;
            out[(size_t)q * K + r]                 = (float)b[r];
            out[(size_t)Q * K + (size_t)q * K + r] = sqrtf(fmaxf(a[r], 0.0f));
        }
    }
}

// ---------------------------------------------------------------------------
extern "C" void kernel_launch(void* const* d_in, const int* in_sizes, int n_in,
                              void* d_out, int out_size) {
    const float* base  = (const float*)d_in[0];
    const float* query = (const float*)d_in[1];

    int N = in_sizes[0] / D128;
    int Q = in_sizes[1] / D128;
    int K = (Q > 0) ? out_size / (2 * Q) : 10;
    if (K <= 0 || K > KG) K = 10;

    float* bsq; cudaGetSymbolAddress((void**)&bsq, g_bsq);

    bsq_kernel<<<(N + 7) / 8, 256>>>(base, bsq, N);

    dim3 grid(NC, (Q + 255) / 256);
    knn_coarse_f32<<<grid, 256>>>(base, query, N, Q);

    merge_kernel<<<(Q + 255) / 256, 256>>>(Q);
    rescore_kernel<<<(Q + 3) / 4, 128>>>(base, query, (float*)d_out, N, Q, K);
}